// round 1
// baseline (speedup 1.0000x reference)
#include <cuda_runtime.h>
#include <math.h>

#define Bv   8
#define Tv   4096
#define Dv   1024
#define Hv   8
#define HDv  128
#define Pv   1024
#define OUTv 1024
#define NWIN 128

// ---------------- scratch (static device globals; no allocation) ----------------
__device__ __align__(16) float g_qk[Hv*Dv];            // 32 KB
__device__ __align__(16) float g_logits[Bv*Hv*Tv];     // 1 MB   [b][h][t]
__device__ __align__(16) float g_m[Bv*Hv*NWIN];        // window max
__device__ __align__(16) float g_invz[Bv*Hv*NWIN];     // 1/denominator
__device__ __align__(16) float g_weight[Bv*Tv*Hv];     // 1 MB   [b][t][h]
__device__ __align__(16) float g_ypart[32*Bv*Hv*Dv];   // 8 MB   [tseg][b][h][d]
__device__ __align__(16) float g_y[Bv*Hv*Dv];          // 256 KB
__device__ __align__(16) float g_aggpart[32*Bv*Pv];    // 1 MB   [dseg][b][p]
__device__ __align__(16) float g_agg[Bv*Pv];           // 32 KB

__device__ __forceinline__ float wredsum(float v){
#pragma unroll
    for (int o = 16; o; o >>= 1) v += __shfl_xor_sync(0xffffffffu, v, o);
    return v;
}
__device__ __forceinline__ float wredmax(float v){
#pragma unroll
    for (int o = 16; o; o >>= 1) v = fmaxf(v, __shfl_xor_sync(0xffffffffu, v, o));
    return v;
}

// ---------------- 1) qk[h,d] = sum_hd w_kv[d, h*128+hd] * query[h,hd] ----------------
// one warp per (h,d); 8192 warps
__global__ void k_qk(const float* __restrict__ w_kv, const float* __restrict__ query){
    int g    = blockIdx.x * 8 + (threadIdx.x >> 5);
    int lane = threadIdx.x & 31;
    int h = g >> 10, d = g & 1023;
    float4 wv = *(const float4*)(w_kv + (size_t)d*2048 + h*128 + lane*4);
    float4 qv = *(const float4*)(query + h*128 + lane*4);
    float s = wv.x*qv.x + wv.y*qv.y + wv.z*qv.z + wv.w*qv.w;
    s = wredsum(s);
    if (lane == 0) g_qk[h*Dv + d] = s;
}

// ---------------- 2) logits[b,h,t] = (x[b,t,:] . qk[h,:]) / sqrt(128) ----------------
// block = 256 (8 warps); each warp handles 4 tokens, all 8 heads. qk staged in smem.
__global__ void k_logits(const float* __restrict__ x){
    __shared__ float qs[Hv*Dv];                 // 32 KB
    int tid = threadIdx.x;
#pragma unroll
    for (int i = 0; i < 8; i++)
        ((float4*)qs)[tid + i*256] = ((const float4*)g_qk)[tid + i*256];
    __syncthreads();

    int warp = tid >> 5, lane = tid & 31;
    int gw = blockIdx.x*8 + warp;               // 8192 warps total
    int b  = gw >> 10;
    int t0 = (gw & 1023) * 4;
    const float* xb = x + ((size_t)b*Tv + t0)*Dv;

    float acc[4][8];
#pragma unroll
    for (int j = 0; j < 4; j++)
#pragma unroll
        for (int h = 0; h < 8; h++) acc[j][h] = 0.f;

#pragma unroll
    for (int i = 0; i < 8; i++){
        int d = i*128 + lane*4;
        float4 xr[4];
#pragma unroll
        for (int j = 0; j < 4; j++) xr[j] = *(const float4*)(xb + (size_t)j*Dv + d);
#pragma unroll
        for (int h = 0; h < 8; h++){
            float4 q = *(const float4*)(qs + h*Dv + d);
#pragma unroll
            for (int j = 0; j < 4; j++){
                acc[j][h] += xr[j].x*q.x;
                acc[j][h] += xr[j].y*q.y;
                acc[j][h] += xr[j].z*q.z;
                acc[j][h] += xr[j].w*q.w;
            }
        }
    }
    const float scale = 0.08838834764831845f;   // 1/sqrt(128)
    float myval = 0.f;
#pragma unroll
    for (int h = 0; h < 8; h++)
#pragma unroll
        for (int j = 0; j < 4; j++){
            float r = wredsum(acc[j][h]);
            if (lane == h*4 + j) myval = r;
        }
    int h = lane >> 2, j = lane & 3;
    g_logits[((size_t)b*Hv + h)*Tv + t0 + j] = myval * scale;
}

// ---------------- 3) per-window softmax stats (max, 1/Z) ----------------
// one warp per (b,h,w); 8192 warps. window w covers t in [32w, 32w+63], masked at T.
__global__ void k_softmax(){
    int tid  = threadIdx.x;
    int gw   = blockIdx.x*8 + (tid >> 5);
    int lane = tid & 31;
    int b = gw >> 10;
    int h = (gw >> 7) & 7;
    int w = gw & 127;
    const float* lp = g_logits + ((size_t)b*Hv + h)*Tv + w*32;
    float l0 = lp[lane];
    int  t1v = (w*32 + lane + 32) < Tv;
    float l1 = t1v ? lp[lane + 32] : -3.0e38f;
    float m = wredmax(fmaxf(l0, l1));
    float z = __expf(l0 - m) + (t1v ? __expf(l1 - m) : 0.f);
    z = wredsum(z);
    if (lane == 0){ g_m[gw] = m; g_invz[gw] = 1.f / z; }
}

// ---------------- 4) weight[b,t,h] = (1/128) * sum_{w covering t} exp(l - m_w)/Z_w ----------------
__global__ void k_weight(){
    int tid = blockIdx.x*blockDim.x + threadIdx.x;   // 262144
    int h = tid & 7;
    int t = (tid >> 3) & 4095;
    int b = tid >> 15;
    float l = g_logits[((size_t)b*Hv + h)*Tv + t];
    int whi = t >> 5;
    int wlo = (whi > 0) ? whi - 1 : 0;
    float v = 0.f;
    for (int w = wlo; w <= whi; w++){
        int idx = (b*Hv + h)*NWIN + w;
        v += __expf(l - g_m[idx]) * g_invz[idx];
    }
    g_weight[((size_t)b*Tv + t)*Hv + h] = v * (1.0f/128.0f);
}

// ---------------- 5) y[b,h,d] = sum_t weight[b,t,h] * x[b,t,d]  (partials over t-segments) ----------------
// grid (tseg=32, dseg=2, b=8), block 128; each thread owns 4 d-channels (float4)
__global__ void k_y(const float* __restrict__ x){
    __shared__ float ws[128*8];
    int tid  = threadIdx.x;
    int tseg = blockIdx.x, dseg = blockIdx.y, b = blockIdx.z;
    int tbase = tseg*128;
    const float4* wsrc = (const float4*)(g_weight + ((size_t)b*Tv + tbase)*Hv);
    ((float4*)ws)[tid]       = wsrc[tid];
    ((float4*)ws)[tid + 128] = wsrc[tid + 128];
    __syncthreads();

    const float* xb = x + ((size_t)b*Tv + tbase)*Dv + dseg*512 + tid*4;
    float acc[8][4];
#pragma unroll
    for (int h = 0; h < 8; h++)
#pragma unroll
        for (int k = 0; k < 4; k++) acc[h][k] = 0.f;

#pragma unroll 4
    for (int tt = 0; tt < 128; tt++){
        float4 x4 = *(const float4*)(xb + (size_t)tt*Dv);
        float4 wa = ((const float4*)ws)[tt*2];
        float4 wb = ((const float4*)ws)[tt*2 + 1];
        float wv[8] = {wa.x, wa.y, wa.z, wa.w, wb.x, wb.y, wb.z, wb.w};
        float xv[4] = {x4.x, x4.y, x4.z, x4.w};
#pragma unroll
        for (int h = 0; h < 8; h++)
#pragma unroll
            for (int k = 0; k < 4; k++) acc[h][k] += wv[h]*xv[k];
    }
    int dbase = dseg*512 + tid*4;
#pragma unroll
    for (int h = 0; h < 8; h++){
        float4 o = make_float4(acc[h][0], acc[h][1], acc[h][2], acc[h][3]);
        *(float4*)(g_ypart + ((((size_t)tseg*Bv + b)*Hv + h)*Dv) + dbase) = o;
    }
}

// ---------------- 6) reduce y partials ----------------
__global__ void k_yred(){
    int i = blockIdx.x*blockDim.x + threadIdx.x;   // 65536
    float s = 0.f;
#pragma unroll
    for (int seg = 0; seg < 32; seg++) s += g_ypart[(size_t)seg*(Bv*Hv*Dv) + i];
    g_y[i] = s;
}

// ---------------- 7) agg partials: agg[b,p] = sum_d w_kv[d, 1024+p] * y[b, p/128, d] ----------------
// grid 32 (dseg of 32 d's), block 256; thread owns p = tid*4..tid*4+3 (same head)
__global__ void k_agg(const float* __restrict__ w_kv){
    int tid  = threadIdx.x;
    int dseg = blockIdx.x;
    int h    = tid >> 5;                  // (tid*4)/128
    float4 acc[8];
#pragma unroll
    for (int b = 0; b < 8; b++) acc[b] = make_float4(0.f,0.f,0.f,0.f);
    int dbase = dseg*32;
    for (int dd = 0; dd < 32; dd++){
        int d = dbase + dd;
        float4 wv = *(const float4*)(w_kv + (size_t)d*2048 + 1024 + tid*4);
#pragma unroll
        for (int b = 0; b < 8; b++){
            float ys = g_y[((size_t)b*Hv + h)*Dv + d];
            acc[b].x += ys*wv.x; acc[b].y += ys*wv.y;
            acc[b].z += ys*wv.z; acc[b].w += ys*wv.w;
        }
    }
#pragma unroll
    for (int b = 0; b < 8; b++)
        *(float4*)(g_aggpart + ((size_t)dseg*Bv + b)*Pv + tid*4) = acc[b];
}

// ---------------- 8) reduce agg partials ----------------
__global__ void k_aggred(){
    int i = blockIdx.x*blockDim.x + threadIdx.x;   // 8192
    float s = 0.f;
#pragma unroll
    for (int seg = 0; seg < 32; seg++) s += g_aggpart[(size_t)seg*(Bv*Pv) + i];
    g_agg[i] = s;
}

// ---------------- 9) out[b,o] = bias[o] + sum_p w_out[o,p]*agg[b,p] ----------------
// block 256 (8 warps = 8 o's), all 8 b per warp; agg staged in smem (32 KB)
__global__ void k_out(const float* __restrict__ w_out, const float* __restrict__ w_b,
                      float* __restrict__ out){
    __shared__ float aggs[Bv*Pv];
    int tid = threadIdx.x;
#pragma unroll
    for (int i = 0; i < 8; i++)
        ((float4*)aggs)[tid + i*256] = ((const float4*)g_agg)[tid + i*256];
    __syncthreads();

    int warp = tid >> 5, lane = tid & 31;
    int o = blockIdx.x*8 + warp;
    float acc[8];
#pragma unroll
    for (int b = 0; b < 8; b++) acc[b] = 0.f;
#pragma unroll
    for (int i = 0; i < 8; i++){
        float4 w4 = *(const float4*)(w_out + (size_t)o*Pv + i*128 + lane*4);
#pragma unroll
        for (int b = 0; b < 8; b++){
            float4 a4 = *(const float4*)(aggs + b*Pv + i*128 + lane*4);
            acc[b] += w4.x*a4.x + w4.y*a4.y + w4.z*a4.z + w4.w*a4.w;
        }
    }
#pragma unroll
    for (int b = 0; b < 8; b++) acc[b] = wredsum(acc[b]);
    if (lane == 0){
        float bias = w_b[o];
#pragma unroll
        for (int b = 0; b < 8; b++) out[(size_t)b*OUTv + o] = acc[b] + bias;
    }
}

// ---------------- launch ----------------
extern "C" void kernel_launch(void* const* d_in, const int* in_sizes, int n_in,
                              void* d_out, int out_size){
    const float* x     = (const float*)d_in[0];
    const float* w_kv  = (const float*)d_in[1];
    const float* query = (const float*)d_in[2];
    const float* w_out = (const float*)d_in[3];
    const float* w_b   = (const float*)d_in[4];
    float* out = (float*)d_out;

    k_qk     <<<1024, 256>>>(w_kv, query);
    k_logits <<<1024, 256>>>(x);
    k_softmax<<<1024, 256>>>();
    k_weight <<<1024, 256>>>();
    dim3 gy(32, 2, 8);
    k_y      <<<gy, 128>>>(x);
    k_yred   <<<256, 256>>>();
    k_agg    <<<32, 256>>>(w_kv);
    k_aggred <<<32, 256>>>();
    k_out    <<<128, 256>>>(w_out, w_b, out);
}

// round 2
// speedup vs baseline: 1.0346x; 1.0346x over previous
#include <cuda_runtime.h>
#include <math.h>

#define Bv   8
#define Tv   4096
#define Dv   1024
#define Hv   8
#define HDv  128
#define Pv   1024
#define OUTv 1024
#define NWIN 128
#define NTSEG 32

// ---------------- scratch (static device globals; no allocation) ----------------
__device__ __align__(16) float g_qk[Hv*Dv];              // 32 KB
__device__ __align__(16) float g_logits[Bv*Hv*Tv];       // 1 MB   [b][h][t]
__device__ __align__(16) float g_weight[Bv*Hv*Tv];       // 1 MB   [b][h][t]
__device__ __align__(16) float g_ypart[NTSEG*Bv*Hv*Dv];  // 8 MB   [tseg][b][h][d]
__device__ __align__(16) float g_aggpart[32*Bv*Pv];      // 1 MB   [dseg][b][p]
__device__ __align__(16) float g_agg[Bv*Pv];             // 32 KB

// ---------------- helpers ----------------
__device__ __forceinline__ float wredsum(float v){
#pragma unroll
    for (int o = 16; o; o >>= 1) v += __shfl_xor_sync(0xffffffffu, v, o);
    return v;
}
__device__ __forceinline__ float wredmax(float v){
#pragma unroll
    for (int o = 16; o; o >>= 1) v = fmaxf(v, __shfl_xor_sync(0xffffffffu, v, o));
    return v;
}
__device__ __forceinline__ unsigned long long fma2(unsigned long long a,
                                                   unsigned long long b,
                                                   unsigned long long c){
    unsigned long long d;
    asm("fma.rn.f32x2 %0, %1, %2, %3;" : "=l"(d) : "l"(a), "l"(b), "l"(c));
    return d;
}
__device__ __forceinline__ unsigned long long add2(unsigned long long a,
                                                   unsigned long long b){
    unsigned long long d;
    asm("add.rn.f32x2 %0, %1, %2;" : "=l"(d) : "l"(a), "l"(b));
    return d;
}
__device__ __forceinline__ float2 unpack2(unsigned long long v){
    float2 r; asm("mov.b64 {%0, %1}, %2;" : "=f"(r.x), "=f"(r.y) : "l"(v)); return r;
}
__device__ __forceinline__ unsigned long long pack2(float lo, float hi){
    unsigned long long v; asm("mov.b64 %0, {%1, %2};" : "=l"(v) : "f"(lo), "f"(hi)); return v;
}
__device__ __forceinline__ unsigned long long wredsum2(unsigned long long v){
#pragma unroll
    for (int o = 16; o; o >>= 1){
        unsigned long long t = __shfl_xor_sync(0xffffffffu, v, o);
        v = add2(v, t);
    }
    return v;
}

// ---------------- 1) qk[h,d] = sum_hd w_kv[d, h*128+hd] * query[h,hd] ----------------
__global__ void k_qk(const float* __restrict__ w_kv, const float* __restrict__ query){
    int g    = blockIdx.x * 8 + (threadIdx.x >> 5);
    int lane = threadIdx.x & 31;
    int h = g >> 10, d = g & 1023;
    float4 wv = *(const float4*)(w_kv + (size_t)d*2048 + h*128 + lane*4);
    float4 qv = *(const float4*)(query + h*128 + lane*4);
    float s = wv.x*qv.x + wv.y*qv.y + wv.z*qv.z + wv.w*qv.w;
    s = wredsum(s);
    if (lane == 0) g_qk[h*Dv + d] = s;
}

// ---------------- 2) logits[b,h,t] = (x[b,t,:] . qk[h,:]) / sqrt(128) ----------------
// block 256 (8 warps); each warp: 4 tokens x 8 heads; packed f32x2 FMA.
__global__ void k_logits(const float* __restrict__ x){
    __shared__ float qs[Hv*Dv];                 // 32 KB
    int tid = threadIdx.x;
#pragma unroll
    for (int i = 0; i < 8; i++)
        ((float4*)qs)[tid + i*256] = ((const float4*)g_qk)[tid + i*256];
    __syncthreads();

    int warp = tid >> 5, lane = tid & 31;
    int gw = blockIdx.x*8 + warp;               // 8192 warps
    int b  = gw >> 10;
    int t0 = (gw & 1023) * 4;
    const float* xb = x + ((size_t)b*Tv + t0)*Dv;

    unsigned long long acc[4][8];               // packed (c01,c23) partial sums
#pragma unroll
    for (int j = 0; j < 4; j++)
#pragma unroll
        for (int h = 0; h < 8; h++) acc[j][h] = 0ull;

#pragma unroll
    for (int i = 0; i < 8; i++){
        int d = i*128 + lane*4;
        ulonglong2 xr[4];
#pragma unroll
        for (int j = 0; j < 4; j++)
            xr[j] = *(const ulonglong2*)(xb + (size_t)j*Dv + d);
#pragma unroll
        for (int h = 0; h < 8; h++){
            ulonglong2 q = *(const ulonglong2*)(qs + h*Dv + d);
#pragma unroll
            for (int j = 0; j < 4; j++){
                acc[j][h] = fma2(xr[j].x, q.x, acc[j][h]);
                acc[j][h] = fma2(xr[j].y, q.y, acc[j][h]);
            }
        }
    }
    const float scale = 0.08838834764831845f;   // 1/sqrt(128)
    float myval = 0.f;
#pragma unroll
    for (int h = 0; h < 8; h++)
#pragma unroll
        for (int j = 0; j < 4; j++){
            unsigned long long r = wredsum2(acc[j][h]);
            float2 p = unpack2(r);
            float s = p.x + p.y;
            if (lane == h*4 + j) myval = s;
        }
    int h = lane >> 2, j = lane & 3;
    g_logits[((size_t)b*Hv + h)*Tv + t0 + j] = myval * scale;
}

// ---------------- 3) fused per-window softmax stats + per-token weights ----------------
// one block per (b,h); 64 blocks x 256 threads
__global__ void k_sw(){
    __shared__ float ls[Tv];                    // 16 KB
    __shared__ float ms[NWIN], zs[NWIN];
    int bh  = blockIdx.x;
    int tid = threadIdx.x;
    const float* lp = g_logits + (size_t)bh*Tv;
#pragma unroll
    for (int i = 0; i < 4; i++)
        ((float4*)ls)[tid + i*256] = ((const float4*)lp)[tid + i*256];
    __syncthreads();

    int warp = tid >> 5, lane = tid & 31;
#pragma unroll
    for (int k = 0; k < 16; k++){
        int w = warp*16 + k;
        float l0 = ls[w*32 + lane];
        int  t1  = w*32 + lane + 32;
        bool v1  = t1 < Tv;
        float l1 = v1 ? ls[t1] : -3.0e38f;
        float m  = wredmax(fmaxf(l0, l1));
        float z  = __expf(l0 - m) + (v1 ? __expf(l1 - m) : 0.f);
        z = wredsum(z);
        if (lane == 0){ ms[w] = m; zs[w] = 1.f / z; }
    }
    __syncthreads();

    float* wp = g_weight + (size_t)bh*Tv;
#pragma unroll
    for (int k = 0; k < 16; k++){
        int t = tid + k*256;
        float l = ls[t];
        int whi = t >> 5;
        float v = __expf(l - ms[whi]) * zs[whi];
        if (whi > 0) v += __expf(l - ms[whi-1]) * zs[whi-1];
        wp[t] = v * (1.0f/128.0f);
    }
}

// ---------------- 4) y partials: y[b,h,d] += weight[b,h,t]*x[b,t,d] over t-segment ----------------
// grid (32 tseg, 1, 8 b), block 256; thread owns 4 d channels. Packed f32x2.
// tseg reversed so the tail of x (still L2-resident from k_logits) is read first.
__global__ void k_y(const float* __restrict__ x){
    __shared__ unsigned long long ws2[Hv*128];  // (w,w) pairs, 8 KB
    int tid  = threadIdx.x;
    int tseg = (NTSEG-1) - blockIdx.x;
    int b    = blockIdx.z;
    int tbase = tseg*128;
#pragma unroll
    for (int k = 0; k < 4; k++){
        int i = tid + k*256;                    // i in [0,1024): h=i>>7, tt=i&127
        int h = i >> 7, tt = i & 127;
        float w = g_weight[((size_t)b*Hv + h)*Tv + tbase + tt];
        ws2[h*128 + tt] = pack2(w, w);
    }
    __syncthreads();

    const float* xb = x + ((size_t)b*Tv + tbase)*Dv + tid*4;
    unsigned long long acc[8][2];
#pragma unroll
    for (int h = 0; h < 8; h++){ acc[h][0] = 0ull; acc[h][1] = 0ull; }

#pragma unroll 8
    for (int tt = 0; tt < 128; tt++){
        ulonglong2 xv = *(const ulonglong2*)(xb + (size_t)tt*Dv);
#pragma unroll
        for (int h = 0; h < 8; h++){
            unsigned long long w2 = ws2[h*128 + tt];
            acc[h][0] = fma2(xv.x, w2, acc[h][0]);
            acc[h][1] = fma2(xv.y, w2, acc[h][1]);
        }
    }
    int dbase = tid*4;
#pragma unroll
    for (int h = 0; h < 8; h++){
        float2 a = unpack2(acc[h][0]);
        float2 c = unpack2(acc[h][1]);
        float4 o = make_float4(a.x, a.y, c.x, c.y);
        *(float4*)(g_ypart + ((((size_t)tseg*Bv + b)*Hv + h)*Dv) + dbase) = o;
    }
}

// ---------------- 5) agg partials (fused y reduction): agg[b,p] = sum_d w_kv_v[d,p]*y[b,h(p),d] ----------------
// grid 32 dsegs (32 d's each), block 256; thread owns p = tid*4..+3 (same head)
__global__ void k_agg(const float* __restrict__ w_kv){
    __shared__ float ys[Bv*Hv*32];              // [b][h][dd], 8 KB
    int tid  = threadIdx.x;
    int dseg = blockIdx.x;
#pragma unroll
    for (int k = 0; k < 8; k++){
        int i = tid + k*256;                    // i in [0,2048): dd=i&31, h=(i>>5)&7, b=i>>8
        int dd = i & 31, h = (i >> 5) & 7, b = i >> 8;
        float s = 0.f;
#pragma unroll
        for (int seg = 0; seg < NTSEG; seg++)
            s += g_ypart[(((size_t)seg*Bv + b)*Hv + h)*Dv + dseg*32 + dd];
        ys[(b*Hv + h)*32 + dd] = s;
    }
    __syncthreads();

    int h = tid >> 5;
    float4 acc[8];
#pragma unroll
    for (int b = 0; b < 8; b++) acc[b] = make_float4(0.f,0.f,0.f,0.f);
    for (int dd = 0; dd < 32; dd++){
        int d = dseg*32 + dd;
        float4 wv = *(const float4*)(w_kv + (size_t)d*2048 + 1024 + tid*4);
#pragma unroll
        for (int b = 0; b < 8; b++){
            float yv = ys[(b*Hv + h)*32 + dd];
            acc[b].x += yv*wv.x; acc[b].y += yv*wv.y;
            acc[b].z += yv*wv.z; acc[b].w += yv*wv.w;
        }
    }
#pragma unroll
    for (int b = 0; b < 8; b++)
        *(float4*)(g_aggpart + ((size_t)dseg*Bv + b)*Pv + tid*4) = acc[b];
}

// ---------------- 6) reduce agg partials ----------------
__global__ void k_aggred(){
    int i = blockIdx.x*blockDim.x + threadIdx.x;   // 8192
    float s = 0.f;
#pragma unroll
    for (int seg = 0; seg < 32; seg++) s += g_aggpart[(size_t)seg*(Bv*Pv) + i];
    g_agg[i] = s;
}

// ---------------- 7) out[b,o] = bias[o] + sum_p w_out[o,p]*agg[b,p] ----------------
__global__ void k_out(const float* __restrict__ w_out, const float* __restrict__ w_b,
                      float* __restrict__ out){
    __shared__ float aggs[Bv*Pv];               // 32 KB
    int tid = threadIdx.x;
#pragma unroll
    for (int i = 0; i < 8; i++)
        ((float4*)aggs)[tid + i*256] = ((const float4*)g_agg)[tid + i*256];
    __syncthreads();

    int warp = tid >> 5, lane = tid & 31;
    int o = blockIdx.x*8 + warp;
    float acc[8];
#pragma unroll
    for (int b = 0; b < 8; b++) acc[b] = 0.f;
#pragma unroll
    for (int i = 0; i < 8; i++){
        float4 w4 = *(const float4*)(w_out + (size_t)o*Pv + i*128 + lane*4);
#pragma unroll
        for (int b = 0; b < 8; b++){
            float4 a4 = *(const float4*)(aggs + b*Pv + i*128 + lane*4);
            acc[b] += w4.x*a4.x + w4.y*a4.y + w4.z*a4.z + w4.w*a4.w;
        }
    }
#pragma unroll
    for (int b = 0; b < 8; b++) acc[b] = wredsum(acc[b]);
    if (lane == 0){
        float bias = w_b[o];
#pragma unroll
        for (int b = 0; b < 8; b++) out[(size_t)b*OUTv + o] = acc[b] + bias;
    }
}

// ---------------- launch ----------------
extern "C" void kernel_launch(void* const* d_in, const int* in_sizes, int n_in,
                              void* d_out, int out_size){
    const float* x     = (const float*)d_in[0];
    const float* w_kv  = (const float*)d_in[1];
    const float* query = (const float*)d_in[2];
    const float* w_out = (const float*)d_in[3];
    const float* w_b   = (const float*)d_in[4];
    float* out = (float*)d_out;

    k_qk     <<<1024, 256>>>(w_kv, query);
    k_logits <<<1024, 256>>>(x);
    k_sw     <<<64, 256>>>();
    dim3 gy(NTSEG, 1, Bv);
    k_y      <<<gy, 256>>>(x);
    k_agg    <<<32, 256>>>(w_kv);
    k_aggred <<<32, 256>>>();
    k_out    <<<128, 256>>>(w_out, w_b, out);
}

// round 4
// speedup vs baseline: 1.0368x; 1.0021x over previous
#include <cuda_runtime.h>
#include <math.h>

#define Bv    8
#define Tv    4096
#define Dv    1024
#define Hv    8
#define Pv    1024
#define OUTv  1024
#define NWIN  128
#define WPB   2              // windows per block
#define WG    (NWIN/WPB)     // 64 window-groups
#define TSPAN 96             // tokens spanned per block (32*WPB + 32)

// ---------------- scratch (static device globals; no allocation) ----------------
__device__ __align__(16) float g_qk[Hv*Dv];             // 32 KB
__device__ __align__(16) float g_ypart[WG*Bv*Hv*Dv];    // 16 MB  [wg][b][h][d]
__device__ __align__(16) float g_y[Bv*Hv*Dv];           // 256 KB
__device__ __align__(16) float g_aggpart[32*Bv*Pv];     // 1 MB   [dseg][b][p]
__device__ __align__(16) float g_agg[Bv*Pv];            // 32 KB

// ---------------- helpers ----------------
__device__ __forceinline__ float wredsum(float v){
#pragma unroll
    for (int o = 16; o; o >>= 1) v += __shfl_xor_sync(0xffffffffu, v, o);
    return v;
}
__device__ __forceinline__ float wredmax(float v){
#pragma unroll
    for (int o = 16; o; o >>= 1) v = fmaxf(v, __shfl_xor_sync(0xffffffffu, v, o));
    return v;
}
__device__ __forceinline__ unsigned long long fma2(unsigned long long a,
                                                   unsigned long long b,
                                                   unsigned long long c){
    unsigned long long d;
    asm("fma.rn.f32x2 %0, %1, %2, %3;" : "=l"(d) : "l"(a), "l"(b), "l"(c));
    return d;
}
__device__ __forceinline__ unsigned long long add2(unsigned long long a,
                                                   unsigned long long b){
    unsigned long long d;
    asm("add.rn.f32x2 %0, %1, %2;" : "=l"(d) : "l"(a), "l"(b));
    return d;
}
__device__ __forceinline__ float2 unpack2(unsigned long long v){
    float2 r; asm("mov.b64 {%0, %1}, %2;" : "=f"(r.x), "=f"(r.y) : "l"(v)); return r;
}
__device__ __forceinline__ unsigned long long pack2(float lo, float hi){
    unsigned long long v; asm("mov.b64 %0, {%1, %2};" : "=l"(v) : "f"(lo), "f"(hi)); return v;
}
__device__ __forceinline__ unsigned long long wredsum2(unsigned long long v){
#pragma unroll
    for (int o = 16; o; o >>= 1){
        unsigned long long t = __shfl_xor_sync(0xffffffffu, v, o);
        v = add2(v, t);
    }
    return v;
}

// ---------------- 1) qk[h,d] = sum_hd w_kv[d, h*128+hd] * query[h,hd] ----------------
__global__ void k_qk(const float* __restrict__ w_kv, const float* __restrict__ query){
    int g    = blockIdx.x * 8 + (threadIdx.x >> 5);
    int lane = threadIdx.x & 31;
    int h = g >> 10, d = g & 1023;
    float4 wv = *(const float4*)(w_kv + (size_t)d*2048 + h*128 + lane*4);
    float4 qv = *(const float4*)(query + h*128 + lane*4);
    float s = wv.x*qv.x + wv.y*qv.y + wv.z*qv.z + wv.w*qv.w;
    s = wredsum(s);
    if (lane == 0) g_qk[h*Dv + d] = s;
}

// ---------------- 2) fused logits + windowed softmax + weighted V-sum partials ----------------
// grid (wg=64, b=8), block 256 (8 warps). Block owns windows {2wg, 2wg+1},
// token span [64wg, 64wg+96). Single DRAM pass over x; phase-C re-read is L2-hot.
__global__ void __launch_bounds__(256, 2) k_fused(const float* __restrict__ x){
    __shared__ float qs[Hv*Dv];                         // 32 KB
    __shared__ float lg[Hv][TSPAN];                     // 3 KB  logits
    __shared__ float cw[Hv][TSPAN];                     // 3 KB  combined weights
    __shared__ unsigned long long cw2[Hv][TSPAN];       // 6 KB  (w,w) pairs

    int tid  = threadIdx.x;
    int wg   = blockIdx.x;
    int b    = blockIdx.y;
    int tbase = wg * 64;

#pragma unroll
    for (int i = 0; i < 8; i++)
        ((float4*)qs)[tid + i*256] = ((const float4*)g_qk)[tid + i*256];
    for (int i = tid; i < Hv*TSPAN; i += 256) ((float*)cw)[i] = 0.f;
    __syncthreads();

    int warp = tid >> 5, lane = tid & 31;
    const float scale = 0.08838834764831845f;           // 1/sqrt(128)

    // ---- phase A: logits for 12 tokens per warp, 3 chunks of 4 ----
#pragma unroll 1
    for (int c = 0; c < 3; c++){
        int tokl = warp*12 + c*4;
        unsigned long long acc[4][8];
#pragma unroll
        for (int j = 0; j < 4; j++)
#pragma unroll
            for (int h = 0; h < 8; h++) acc[j][h] = 0ull;

        const float* rp[4];
#pragma unroll
        for (int j = 0; j < 4; j++){
            int t = tbase + tokl + j;
            t = t < Tv ? t : Tv - 1;                    // clamp OOB rows (masked later)
            rp[j] = x + ((size_t)b*Tv + t)*Dv + lane*4; // FIXED: batch offset
        }
#pragma unroll
        for (int i = 0; i < 8; i++){
            ulonglong2 xr[4];
#pragma unroll
            for (int j = 0; j < 4; j++)
                xr[j] = *(const ulonglong2*)(rp[j] + i*128);
#pragma unroll
            for (int h = 0; h < 8; h++){
                ulonglong2 q = *(const ulonglong2*)(qs + h*Dv + i*128 + lane*4);
#pragma unroll
                for (int j = 0; j < 4; j++){
                    acc[j][h] = fma2(xr[j].x, q.x, acc[j][h]);
                    acc[j][h] = fma2(xr[j].y, q.y, acc[j][h]);
                }
            }
        }
        float my = 0.f;
#pragma unroll
        for (int h = 0; h < 8; h++)
#pragma unroll
            for (int j = 0; j < 4; j++){
                unsigned long long r = wredsum2(acc[j][h]);
                float2 p = unpack2(r);
                float s = (p.x + p.y) * scale;
                if (lane == h*4 + j) my = s;
            }
        int tok = tokl + (lane & 3);
        lg[lane >> 2][tok] = (tbase + tok < Tv) ? my : -3.0e38f;
    }
    __syncthreads();

    // ---- phase B: two windows' softmax per head (warp == head) ----
#pragma unroll
    for (int wi = 0; wi < WPB; wi++){
        int t0l = wi*32;
        float l0 = lg[warp][t0l + lane];
        float l1 = lg[warp][t0l + lane + 32];
        float m  = wredmax(fmaxf(l0, l1));
        float e0 = __expf(l0 - m);
        float e1 = __expf(l1 - m);
        float z  = wredsum(e0 + e1);
        float inv = (1.0f/128.0f) / z;
        cw[warp][t0l + lane]      += e0 * inv;
        cw[warp][t0l + lane + 32] += e1 * inv;
    }
    __syncthreads();
    for (int i = tid; i < Hv*TSPAN; i += 256){
        float v = ((float*)cw)[i];
        ((unsigned long long*)cw2)[i] = pack2(v, v);
    }
    __syncthreads();

    // ---- phase C: y partial, thread owns 4 d channels; x re-read hits L2 ----
    int tmax = TSPAN < (Tv - tbase) ? TSPAN : (Tv - tbase);
    const float* xb = x + ((size_t)b*Tv + tbase)*Dv + tid*4;
    unsigned long long acc[8][2];
#pragma unroll
    for (int h = 0; h < 8; h++){ acc[h][0] = 0ull; acc[h][1] = 0ull; }

#pragma unroll 4
    for (int tt = 0; tt < tmax; tt++){
        ulonglong2 xv = *(const ulonglong2*)(xb + (size_t)tt*Dv);
#pragma unroll
        for (int h = 0; h < 8; h++){
            unsigned long long w2 = cw2[h][tt];
            acc[h][0] = fma2(xv.x, w2, acc[h][0]);
            acc[h][1] = fma2(xv.y, w2, acc[h][1]);
        }
    }
    int dbase = tid*4;
#pragma unroll
    for (int h = 0; h < 8; h++){
        float2 a = unpack2(acc[h][0]);
        float2 c = unpack2(acc[h][1]);
        float4 o = make_float4(a.x, a.y, c.x, c.y);
        *(float4*)(g_ypart + ((((size_t)wg*Bv + b)*Hv + h)*Dv) + dbase) = o;
    }
}

// ---------------- 3) reduce y partials over window-groups ----------------
__global__ void k_yred(){
    int i = blockIdx.x*blockDim.x + threadIdx.x;        // 65536 = b*h*d
    float s = 0.f;
#pragma unroll
    for (int seg = 0; seg < WG; seg++) s += g_ypart[(size_t)seg*(Bv*Hv*Dv) + i];
    g_y[i] = s;
}

// ---------------- 4) agg partials: agg[b,p] = sum_d w_kv_v[d,p] * y[b, p/128, d] ----------------
__global__ void k_agg(const float* __restrict__ w_kv){
    int tid  = threadIdx.x;
    int dseg = blockIdx.x;
    int h    = tid >> 5;
    float4 acc[8];
#pragma unroll
    for (int b = 0; b < 8; b++) acc[b] = make_float4(0.f,0.f,0.f,0.f);
    int dbase = dseg*32;
    for (int dd = 0; dd < 32; dd++){
        int d = dbase + dd;
        float4 wv = *(const float4*)(w_kv + (size_t)d*2048 + 1024 + tid*4);
#pragma unroll
        for (int b = 0; b < 8; b++){
            float yv = g_y[((size_t)b*Hv + h)*Dv + d];
            acc[b].x += yv*wv.x; acc[b].y += yv*wv.y;
            acc[b].z += yv*wv.z; acc[b].w += yv*wv.w;
        }
    }
#pragma unroll
    for (int b = 0; b < 8; b++)
        *(float4*)(g_aggpart + ((size_t)dseg*Bv + b)*Pv + tid*4) = acc[b];
}

// ---------------- 5) reduce agg partials ----------------
__global__ void k_aggred(){
    int i = blockIdx.x*blockDim.x + threadIdx.x;        // 8192
    float s = 0.f;
#pragma unroll
    for (int seg = 0; seg < 32; seg++) s += g_aggpart[(size_t)seg*(Bv*Pv) + i];
    g_agg[i] = s;
}

// ---------------- 6) out[b,o] = bias[o] + sum_p w_out[o,p]*agg[b,p] ----------------
__global__ void k_out(const float* __restrict__ w_out, const float* __restrict__ w_b,
                      float* __restrict__ out){
    __shared__ float aggs[Bv*Pv];                       // 32 KB
    int tid = threadIdx.x;
#pragma unroll
    for (int i = 0; i < 8; i++)
        ((float4*)aggs)[tid + i*256] = ((const float4*)g_agg)[tid + i*256];
    __syncthreads();

    int warp = tid >> 5, lane = tid & 31;
    int o = blockIdx.x*8 + warp;
    float acc[8];
#pragma unroll
    for (int b = 0; b < 8; b++) acc[b] = 0.f;
#pragma unroll
    for (int i = 0; i < 8; i++){
        float4 w4 = *(const float4*)(w_out + (size_t)o*Pv + i*128 + lane*4);
#pragma unroll
        for (int b = 0; b < 8; b++){
            float4 a4 = *(const float4*)(aggs + b*Pv + i*128 + lane*4);
            acc[b] += w4.x*a4.x + w4.y*a4.y + w4.z*a4.z + w4.w*a4.w;
        }
    }
#pragma unroll
    for (int b = 0; b < 8; b++) acc[b] = wredsum(acc[b]);
    if (lane == 0){
        float bias = w_b[o];
#pragma unroll
        for (int b = 0; b < 8; b++) out[(size_t)b*OUTv + o] = acc[b] + bias;
    }
}

// ---------------- launch ----------------
extern "C" void kernel_launch(void* const* d_in, const int* in_sizes, int n_in,
                              void* d_out, int out_size){
    const float* x     = (const float*)d_in[0];
    const float* w_kv  = (const float*)d_in[1];
    const float* query = (const float*)d_in[2];
    const float* w_out = (const float*)d_in[3];
    const float* w_b   = (const float*)d_in[4];
    float* out = (float*)d_out;

    k_qk    <<<1024, 256>>>(w_kv, query);
    dim3 gf(WG, Bv);
    k_fused <<<gf, 256>>>(x);
    k_yred  <<<256, 256>>>();
    k_agg   <<<32, 256>>>(w_kv);
    k_aggred<<<32, 256>>>();
    k_out   <<<128, 256>>>(w_out, w_b, out);
}